// round 14
// baseline (speedup 1.0000x reference)
#include <cuda_runtime.h>
#include <cuda_bf16.h>
#include <stdint.h>

#define NSRC 3
#define ELEM_X (2*2048*512)
#define ELEM_Y (3*2*2048*512)
#define WSTR   (512*512)

__device__ __nv_bfloat16 g_xh[ELEM_X], g_xl[ELEM_X];
__device__ __nv_bfloat16 g_yh[ELEM_Y], g_yl[ELEM_Y];
__device__ __nv_bfloat16 g_wh[8*WSTR], g_wl[8*WSTR];
__device__ __nv_bfloat16 g_qh[ELEM_X], g_ql[ELEM_X];
__device__ __nv_bfloat16 g_kh[ELEM_Y], g_kl[ELEM_Y];
__device__ __nv_bfloat16 g_vth[ELEM_Y], g_vtl[ELEM_Y];   // V^T: [src*512+n][4096]
__device__ __nv_bfloat16 g_oh[ELEM_X], g_ol[ELEM_X];

#define SWZ(o) ((uint32_t)(o) ^ ((((uint32_t)(o)) >> 3) & 0x70u))
#define ID_128 0x8200490u   /* kind::f16 f32acc bf16 M=128 N=128 */
#define ID_PV  0x8100490u   /* kind::f16 f32acc bf16 M=128 N=64  */

#if defined(__CUDA_ARCH_FEAT_SM103_ALL) || defined(__CUDA_ARCH_FEAT_SM100_ALL) || !defined(__CUDA_ARCH__)
#define HAS_TC5 1
#else
#define HAS_TC5 0
#endif

__device__ __forceinline__ uint32_t elect1() {
    uint32_t p;
    asm volatile("{\n\t.reg .pred p;\n\telect.sync _|p, 0xFFFFFFFF;\n\tselp.b32 %0,1,0,p;\n\t}" : "=r"(p));
    return p;
}
__device__ __forceinline__ uint32_t s2u(const void* p) {
    uint32_t a;
    asm("{ .reg .u64 t; cvta.to.shared.u64 t, %1; cvt.u32.u64 %0, t; }" : "=r"(a) : "l"(p));
    return a;
}
__device__ __forceinline__ uint64_t dk(uint32_t a) {
    return (2ull<<61)|(1ull<<46)|(64ull<<32)|(1ull<<16)|((uint64_t)(a>>4)&0x3FFFull);
}

#define MBAR_INIT(a,n) asm volatile("mbarrier.init.shared.b64 [%0], %1;" :: "r"(a), "r"(n) : "memory")
#define MBAR_WAIT(a,ph) asm volatile("{\n\t.reg .pred P1;\n\tLW%=:\n\t" \
    "mbarrier.try_wait.parity.acquire.cta.shared::cta.b64 P1, [%0], %1, 0x989680;\n\t" \
    "@P1 bra.uni LD%=;\n\tbra.uni LW%=;\n\tLD%=:\n\t}" :: "r"(a), "r"(ph) : "memory")
#define MBAR_ARRIVE(a) asm volatile("mbarrier.arrive.release.cta.shared::cta.b64 _, [%0];" :: "r"(a) : "memory")
#define FPROXY()       asm volatile("fence.proxy.async.shared::cta;" ::: "memory")
#define CPA16(d,s)     asm volatile("cp.async.cg.shared.global [%0], [%1], 16;" :: "r"(d), "l"(s))
#define CPA_COMMIT()   asm volatile("cp.async.commit_group;" ::: "memory")
#define CPA_WAIT0()    asm volatile("cp.async.wait_group 0;" ::: "memory")
#define CPA_WAIT1()    asm volatile("cp.async.wait_group 1;" ::: "memory")
#define CPA_WAIT2()    asm volatile("cp.async.wait_group 2;" ::: "memory")
#define CPA_MBAR(a)    asm volatile("cp.async.mbarrier.arrive.noinc.shared::cta.b64 [%0];" :: "r"(a) : "memory")

#if HAS_TC5
__device__ __forceinline__ void mma16(uint32_t d, uint64_t a, uint64_t b, uint32_t id, uint32_t acc) {
    asm volatile("{\n\t.reg .pred p;\n\tsetp.ne.u32 p, %4, 0;\n\t"
        "tcgen05.mma.cta_group::1.kind::f16 [%0], %1, %2, %3, {%5,%5,%5,%5}, p;\n\t}"
        :: "r"(d), "l"(a), "l"(b), "r"(id), "r"(acc), "r"(0u) : "memory");
}
#define TC_ALLOC(a,n)  asm volatile("tcgen05.alloc.cta_group::1.sync.aligned.shared::cta.b32 [%0], %1;" :: "r"(a), "r"(n) : "memory")
#define TC_RELQ()      asm volatile("tcgen05.relinquish_alloc_permit.cta_group::1.sync.aligned;")
#define TC_DEALLOC(t,n) asm volatile("tcgen05.dealloc.cta_group::1.sync.aligned.b32 %0, %1;" :: "r"(t), "r"(n))
#define TC_COMMIT(a)   asm volatile("tcgen05.commit.cta_group::1.mbarrier::arrive::one.shared::cluster.b64 [%0];" :: "r"(a) : "memory")
#define TC_FA()        asm volatile("tcgen05.fence::after_thread_sync;" ::: "memory")
#define TC_FB()        asm volatile("tcgen05.fence::before_thread_sync;" ::: "memory")
#define TC_WLD()       asm volatile("tcgen05.wait::ld.sync.aligned;" ::: "memory")
#define LDTM32(r, a) asm volatile( \
    "tcgen05.ld.sync.aligned.32x32b.x32.b32 " \
    "{%0,%1,%2,%3,%4,%5,%6,%7,%8,%9,%10,%11,%12,%13,%14,%15," \
    "%16,%17,%18,%19,%20,%21,%22,%23,%24,%25,%26,%27,%28,%29,%30,%31}, [%32];" \
    : "=r"((r)[0]),"=r"((r)[1]),"=r"((r)[2]),"=r"((r)[3]),"=r"((r)[4]),"=r"((r)[5]),"=r"((r)[6]),"=r"((r)[7]), \
      "=r"((r)[8]),"=r"((r)[9]),"=r"((r)[10]),"=r"((r)[11]),"=r"((r)[12]),"=r"((r)[13]),"=r"((r)[14]),"=r"((r)[15]), \
      "=r"((r)[16]),"=r"((r)[17]),"=r"((r)[18]),"=r"((r)[19]),"=r"((r)[20]),"=r"((r)[21]),"=r"((r)[22]),"=r"((r)[23]), \
      "=r"((r)[24]),"=r"((r)[25]),"=r"((r)[26]),"=r"((r)[27]),"=r"((r)[28]),"=r"((r)[29]),"=r"((r)[30]),"=r"((r)[31]) \
    : "r"(a))
#else
__device__ __forceinline__ void mma16(uint32_t, uint64_t, uint64_t, uint32_t, uint32_t) { __trap(); }
#define TC_ALLOC(a,n)   __trap()
#define TC_RELQ()       __trap()
#define TC_DEALLOC(t,n) __trap()
#define TC_COMMIT(a)    __trap()
#define TC_FA()         ((void)0)
#define TC_FB()         ((void)0)
#define TC_WLD()        ((void)0)
#define LDTM32(r, a) do { _Pragma("unroll") for (int _i = 0; _i < 32; _i++) (r)[_i] = 0u; __trap(); } while (0)
#endif

__device__ __forceinline__ uint32_t packh(__nv_bfloat16 a, __nv_bfloat16 b) {
    __nv_bfloat162 v; v.x = a; v.y = b;
    return *reinterpret_cast<uint32_t*>(&v);
}
__device__ __forceinline__ uint32_t pack2(float lo, float hi) {
    uint32_t r;
    asm("cvt.rn.bf16x2.f32 %0, %1, %2;" : "=r"(r) : "f"(hi), "f"(lo));
    return r;
}

// ------------------------- prep kernels -----------------------------------
__global__ void splitk(const float* __restrict__ in, __nv_bfloat16* __restrict__ oh,
                       __nv_bfloat16* __restrict__ ol, int n4) {
    for (int i = blockIdx.x * blockDim.x + threadIdx.x; i < n4; i += gridDim.x * blockDim.x) {
        float4 v = ((const float4*)in)[i];
        __nv_bfloat16 h0 = __float2bfloat16_rn(v.x), h1 = __float2bfloat16_rn(v.y);
        __nv_bfloat16 h2 = __float2bfloat16_rn(v.z), h3 = __float2bfloat16_rn(v.w);
        __nv_bfloat16 l0 = __float2bfloat16_rn(v.x - __bfloat162float(h0));
        __nv_bfloat16 l1 = __float2bfloat16_rn(v.y - __bfloat162float(h1));
        __nv_bfloat16 l2 = __float2bfloat16_rn(v.z - __bfloat162float(h2));
        __nv_bfloat16 l3 = __float2bfloat16_rn(v.w - __bfloat162float(h3));
        *(uint2*)(oh + 4 * (size_t)i) = make_uint2(packh(h0, h1), packh(h2, h3));
        *(uint2*)(ol + 4 * (size_t)i) = make_uint2(packh(l0, l1), packh(l2, l3));
    }
}

// all 8 weight matrices in one launch: z=0 Wq, 1..3 Wk, 4..6 Wv, 7 Wp
__global__ void wtsk(const float* __restrict__ Wq, const float* __restrict__ Wk,
                     const float* __restrict__ Wv, const float* __restrict__ Wp,
                     __nv_bfloat16* __restrict__ th, __nv_bfloat16* __restrict__ tl) {
    __shared__ float t[32][33];
    int m = blockIdx.z;
    const float* Wm = (m == 0) ? Wq : (m <= 3) ? Wk + (size_t)(m - 1) * WSTR
                    : (m <= 6) ? Wv + (size_t)(m - 4) * WSTR : Wp;
    int k0 = blockIdx.x * 32, n0 = blockIdx.y * 32;
    t[threadIdx.y][threadIdx.x] = Wm[(size_t)(k0 + threadIdx.y) * 512 + n0 + threadIdx.x];
    __syncthreads();
    float v = t[threadIdx.x][threadIdx.y];
    size_t di = (size_t)m * WSTR + (size_t)(n0 + threadIdx.y) * 512 + k0 + threadIdx.x;
    __nv_bfloat16 h = __float2bfloat16_rn(v);
    th[di] = h;
    tl[di] = __float2bfloat16_rn(v - __bfloat162float(h));
}

// ------------------------- unified projection GEMM -------------------------
__global__ __launch_bounds__(256) void proj(
    const __nv_bfloat16* __restrict__ xh, const __nv_bfloat16* __restrict__ xl,
    const __nv_bfloat16* __restrict__ yh, const __nv_bfloat16* __restrict__ yl,
    const __nv_bfloat16* __restrict__ wh, const __nv_bfloat16* __restrict__ wl,
    const float* __restrict__ bq, const float* __restrict__ bk, const float* __restrict__ bv,
    __nv_bfloat16* __restrict__ Qh, __nv_bfloat16* __restrict__ Ql,
    __nv_bfloat16* __restrict__ Kh, __nv_bfloat16* __restrict__ Kl,
    __nv_bfloat16* __restrict__ Vth, __nv_bfloat16* __restrict__ Vtl)
{
    extern __shared__ char sm[];
    const uint32_t sb = s2u(sm);
    const int tid = threadIdx.x, wid = tid >> 5, lane = tid & 31;
    const int bm = blockIdx.y * 128, bn = blockIdx.x * 128;
    const int z = blockIdx.z;

    const __nv_bfloat16 *ah, *al, *bhp, *blp;
    const float* bias;
    __nv_bfloat16 *ohp, *olp;
    float scale;
    int mode;
    if (z == 0) {
        ah = xh; al = xl; bhp = wh; blp = wl; bias = bq;
        ohp = Qh; olp = Ql; scale = 0.125f; mode = 1;
    } else if (z <= 3) {
        int s = z - 1; size_t off = (size_t)s * 2 * 2048 * 512;
        ah = yh + off; al = yl + off;
        bhp = wh + (size_t)(1 + s) * WSTR; blp = wl + (size_t)(1 + s) * WSTR;
        bias = bk + 512 * s; ohp = Kh + off; olp = Kl + off; scale = 1.0f; mode = 1;
    } else {
        int s = z - 4; size_t off = (size_t)s * 2 * 2048 * 512;
        ah = yh + off; al = yl + off;
        bhp = wh + (size_t)(4 + s) * WSTR; blp = wl + (size_t)(4 + s) * WSTR;
        bias = bv + 512 * s; ohp = Vth + off; olp = Vtl + off; scale = 1.0f; mode = 2;
    }

    if (wid == 0) { TC_ALLOC(sb, 128); TC_RELQ(); }
    if (tid == 0) MBAR_INIT(sb + 8, 1);
    __syncthreads();
    uint32_t tm;
    asm volatile("ld.shared.b32 %0, [%1];" : "=r"(tm) : "r"(sb));

    auto stage = [&](int kc, int buf) {
#pragma unroll
        for (int i = 0; i < 16; i++) {
            int idx = tid + i * 256;
            int t = idx >> 10, r = (idx >> 3) & 127, u = idx & 7;
            const __nv_bfloat16* src = (t == 0) ? ah : (t == 1) ? al : (t == 2) ? bhp : blp;
            int grow = ((t < 2) ? bm : bn) + r;
            CPA16(sb + 1024 + buf * 65536 + t * 16384 + SWZ(r * 128 + u * 16),
                  src + (size_t)grow * 512 + kc * 64 + u * 8);
        }
        CPA_COMMIT();
    };

    stage(0, 0);
    stage(1, 1);
    for (int kc = 0; kc < 8; kc++) {
        int buf = kc % 3;
        if (kc >= 1) MBAR_WAIT(sb + 8, (kc - 1) & 1);
        if (kc + 2 < 8) stage(kc + 2, (kc + 2) % 3);
        if (kc < 6) CPA_WAIT2(); else if (kc == 6) CPA_WAIT1(); else CPA_WAIT0();
        FPROXY(); __syncthreads();
        if (wid == 0 && elect1()) {
            uint32_t ab = sb + 1024 + buf * 65536;
            uint64_t dah = dk(ab), dal = dk(ab + 16384);
            uint64_t dbh = dk(ab + 32768), dbl = dk(ab + 49152);
#pragma unroll
            for (int s = 0; s < 4; s++) mma16(tm, dah + 2*s, dbh + 2*s, ID_128, (kc > 0) || (s > 0));
#pragma unroll
            for (int s = 0; s < 4; s++) mma16(tm, dah + 2*s, dbl + 2*s, ID_128, 1);
#pragma unroll
            for (int s = 0; s < 4; s++) mma16(tm, dal + 2*s, dbh + 2*s, ID_128, 1);
            TC_COMMIT(sb + 8);
        }
    }
    MBAR_WAIT(sb + 8, 1);
    TC_FA();

    const int r = (wid & 3) * 32 + lane, cb = (wid >> 2) * 64;
    uint32_t u[64];
    LDTM32(u, tm + cb);
    LDTM32(u + 32, tm + cb + 32);
    TC_WLD(); TC_FB();
    float f[64];
#pragma unroll
    for (int j = 0; j < 64; j++)
        f[j] = scale * (__uint_as_float(u[j]) + bias[bn + cb + j]);
    if (mode == 1) {
        uint32_t hw[32], lw[32];
#pragma unroll
        for (int j = 0; j < 32; j++) {
            __nv_bfloat16 h0 = __float2bfloat16_rn(f[2*j]), h1 = __float2bfloat16_rn(f[2*j+1]);
            hw[j] = packh(h0, h1);
            lw[j] = packh(__float2bfloat16_rn(f[2*j]   - __bfloat162float(h0)),
                          __float2bfloat16_rn(f[2*j+1] - __bfloat162float(h1)));
        }
        size_t o = (size_t)(bm + r) * 512 + bn + cb;
#pragma unroll
        for (int g = 0; g < 8; g++) {
            *(uint4*)(ohp + o + g * 8) = make_uint4(hw[g*4], hw[g*4+1], hw[g*4+2], hw[g*4+3]);
            *(uint4*)(olp + o + g * 8) = make_uint4(lw[g*4], lw[g*4+1], lw[g*4+2], lw[g*4+3]);
        }
    } else {
#pragma unroll
        for (int j = 0; j < 64; j++) {
            __nv_bfloat16 h0 = __float2bfloat16_rn(f[j]);
            __nv_bfloat16 l0 = __float2bfloat16_rn(f[j] - __bfloat162float(h0));
            size_t o = (size_t)(bn + cb + j) * 4096 + bm + r;
            ohp[o] = h0;
            olp[o] = l0;
        }
    }
    __syncthreads();
    if (wid == 0) TC_DEALLOC(tm, 128);
}

// ------------------------- out-projection GEMM (fp32 out) ------------------
__global__ __launch_bounds__(256) void tgemm0(
    const __nv_bfloat16* __restrict__ ah, const __nv_bfloat16* __restrict__ al,
    const __nv_bfloat16* __restrict__ bh, const __nv_bfloat16* __restrict__ bl,
    const float* __restrict__ bias, float* __restrict__ of)
{
    extern __shared__ char sm[];
    const uint32_t sb = s2u(sm);
    const int tid = threadIdx.x, wid = tid >> 5, lane = tid & 31;
    const int bm = blockIdx.y * 128, bn = blockIdx.x * 128;

    if (wid == 0) { TC_ALLOC(sb, 128); TC_RELQ(); }
    if (tid == 0) MBAR_INIT(sb + 8, 1);
    __syncthreads();
    uint32_t tm;
    asm volatile("ld.shared.b32 %0, [%1];" : "=r"(tm) : "r"(sb));

    auto stage = [&](int kc, int buf) {
#pragma unroll
        for (int i = 0; i < 16; i++) {
            int idx = tid + i * 256;
            int t = idx >> 10, r = (idx >> 3) & 127, u = idx & 7;
            const __nv_bfloat16* src = (t == 0) ? ah : (t == 1) ? al : (t == 2) ? bh : bl;
            int grow = ((t < 2) ? bm : bn) + r;
            CPA16(sb + 1024 + buf * 65536 + t * 16384 + SWZ(r * 128 + u * 16),
                  src + (size_t)grow * 512 + kc * 64 + u * 8);
        }
        CPA_COMMIT();
    };

    stage(0, 0);
    stage(1, 1);
    for (int kc = 0; kc < 8; kc++) {
        int buf = kc % 3;
        if (kc >= 1) MBAR_WAIT(sb + 8, (kc - 1) & 1);
        if (kc + 2 < 8) stage(kc + 2, (kc + 2) % 3);
        if (kc < 6) CPA_WAIT2(); else if (kc == 6) CPA_WAIT1(); else CPA_WAIT0();
        FPROXY(); __syncthreads();
        if (wid == 0 && elect1()) {
            uint32_t ab = sb + 1024 + buf * 65536;
            uint64_t dah = dk(ab), dal = dk(ab + 16384);
            uint64_t dbh = dk(ab + 32768), dbl = dk(ab + 49152);
#pragma unroll
            for (int s = 0; s < 4; s++) mma16(tm, dah + 2*s, dbh + 2*s, ID_128, (kc > 0) || (s > 0));
#pragma unroll
            for (int s = 0; s < 4; s++) mma16(tm, dah + 2*s, dbl + 2*s, ID_128, 1);
#pragma unroll
            for (int s = 0; s < 4; s++) mma16(tm, dal + 2*s, dbh + 2*s, ID_128, 1);
            TC_COMMIT(sb + 8);
        }
    }
    MBAR_WAIT(sb + 8, 1);
    TC_FA();

    const int r = (wid & 3) * 32 + lane, cb = (wid >> 2) * 64;
    uint32_t u[64];
    LDTM32(u, tm + cb);
    LDTM32(u + 32, tm + cb + 32);
    TC_WLD(); TC_FB();
    float* p = of + (size_t)(bm + r) * 512 + bn + cb;
#pragma unroll
    for (int g = 0; g < 16; g++) {
        float4 o4;
        o4.x = __uint_as_float(u[g*4+0]) + bias[bn + cb + g*4+0];
        o4.y = __uint_as_float(u[g*4+1]) + bias[bn + cb + g*4+1];
        o4.z = __uint_as_float(u[g*4+2]) + bias[bn + cb + g*4+2];
        o4.w = __uint_as_float(u[g*4+3]) + bias[bn + cb + g*4+3];
        *(float4*)(p + g * 4) = o4;
    }
    __syncthreads();
    if (wid == 0) TC_DEALLOC(tm, 128);
}
#define GSM (1024 + 3 * 65536)

// ------------------ warp-specialized tcgen05 attention (544 thr) -----------
// warps 0..15: loads + softmax.  warp 16: MMA issuer.
// mbars: s=8, pv=16, kf0=24, kf1=32, vf0=40, vf1=48 (count 512, noinc),
//        pr=56 (count 512, softmax arrive after P store).
#define A_Q   2048
#define A_K0  34816
#define A_V0  100352
#define A_PH  165888
#define A_PL  198656
#define A_SMEM 231424
#define NT 48

__global__ __launch_bounds__(544) void attn(
    const __nv_bfloat16* __restrict__ qh, const __nv_bfloat16* __restrict__ ql,
    const __nv_bfloat16* __restrict__ kh, const __nv_bfloat16* __restrict__ kl,
    const __nv_bfloat16* __restrict__ vth, const __nv_bfloat16* __restrict__ vtl,
    __nv_bfloat16* __restrict__ oh, __nv_bfloat16* __restrict__ ol)
{
    extern __shared__ char sm[];
    const uint32_t sb = s2u(sm);
    float* lsumf = (float*)(sm + 64);
    const int tid = threadIdx.x, wid = tid >> 5, lane = tid & 31;
    const int q0 = blockIdx.x * 128, h = blockIdx.y, b = blockIdx.z;

    if (wid == 0) { TC_ALLOC(sb, 512); TC_RELQ(); }
    if (tid == 0) {
        MBAR_INIT(sb + 8, 1);  MBAR_INIT(sb + 16, 1);
        MBAR_INIT(sb + 24, 512); MBAR_INIT(sb + 32, 512);
        MBAR_INIT(sb + 40, 512); MBAR_INIT(sb + 48, 512);
        MBAR_INIT(sb + 56, 512);
    }
    if (tid < 384) lsumf[tid] = 0.f;
    __syncthreads();
    uint32_t tm;
    asm volatile("ld.shared.b32 %0, [%1];" : "=r"(tm) : "r"(sb));
    const uint32_t tmo = tm + 256;

    auto ldK = [&](int g1, int buf) {       // tid<512: 4 cp.async -> kf[buf]
        int srcI = g1 >> 4, kt = g1 & 15;
        const size_t kvb = ((size_t)(srcI * 2 + b)) * 2048 * 512 + h * 64;
        uint32_t base = sb + A_K0 + buf * 32768;
#pragma unroll
        for (int i = 0; i < 4; i++) {
            int idx = tid + i * 512;
            int mat = idx >> 10, rem = idx & 1023;
            int rr = rem >> 3, u = rem & 7;
            const __nv_bfloat16* s0 = mat ? kl : kh;
            CPA16(base + mat * 16384 + SWZ(rr * 128 + u * 16),
                  s0 + kvb + (size_t)(kt * 128 + rr) * 512 + u * 8);
        }
        CPA_MBAR(sb + 24 + buf * 8);
    };
    auto ldV = [&](int g1, int buf) {
        int srcI = g1 >> 4, kt = g1 & 15;
        const size_t vtb = ((size_t)(srcI * 512 + h * 64)) * 4096 + b * 2048;
        uint32_t base = sb + A_V0 + buf * 32768;
#pragma unroll
        for (int i = 0; i < 4; i++) {
            int idx = tid + i * 512;
            int mat = idx >> 10, rem = idx & 1023;
            int d = rem >> 4, u = rem & 15;
            const __nv_bfloat16* s0 = mat ? vtl : vth;
            CPA16(base + mat * 16384 + (u >> 3) * 8192 + SWZ(d * 128 + (u & 7) * 16),
                  s0 + vtb + (size_t)d * 4096 + kt * 128 + u * 8);
        }
        CPA_MBAR(sb + 40 + buf * 8);
    };

    if (tid < 512) {
        // Q tile hi/lo (once)
#pragma unroll
        for (int i = 0; i < 4; i++) {
            int idx = tid + i * 512;
            int t = idx >> 10, r = (idx >> 3) & 127, u = idx & 7;
            const __nv_bfloat16* src = t ? ql : qh;
            uint4 v = *(const uint4*)(src + (size_t)(b * 2048 + q0 + r) * 512 + h * 64 + u * 8);
            *(uint4*)(sm + A_Q + t * 16384 + SWZ(r * 128 + u * 16)) = v;
        }
        ldK(0, 0); ldV(0, 0); ldK(1, 1);
    }
    FPROXY(); __syncthreads();

    if (wid == 16) {
        // ---------------- MMA issuer ----------------
        if (elect1()) {
            uint64_t dqh = dk(sb + A_Q), dql = dk(sb + A_Q + 16384);
            uint64_t dph = dk(sb + A_PH), dpl = dk(sb + A_PL);
            // S(0)
            MBAR_WAIT(sb + 24, 0);
            FPROXY();
            {
                uint64_t dkh = dk(sb + A_K0), dkl = dk(sb + A_K0 + 16384);
#pragma unroll
                for (int s = 0; s < 4; s++) mma16(tm, dqh + 2*s, dkh + 2*s, ID_128, s > 0);
#pragma unroll
                for (int s = 0; s < 4; s++) mma16(tm, dqh + 2*s, dkl + 2*s, ID_128, 1);
#pragma unroll
                for (int s = 0; s < 4; s++) mma16(tm, dql + 2*s, dkh + 2*s, ID_128, 1);
                TC_COMMIT(sb + 8);
            }
            for (int g = 0; g < NT; g++) {
                if (g + 1 < NT) {                      // S(g+1)
                    MBAR_WAIT(sb + 24 + ((g + 1) & 1) * 8, ((g + 1) >> 1) & 1);
                    FPROXY();
                    uint32_t kb = sb + A_K0 + ((g + 1) & 1) * 32768;
                    uint64_t dkh = dk(kb), dkl = dk(kb + 16384);
                    uint32_t tms = tm + ((g + 1) & 1) * 128;
#pragma unroll
                    for (int s = 0; s < 4; s++) mma16(tms, dqh + 2*s, dkh + 2*s, ID_128, s > 0);
#pragma unroll
                    for (int s = 0; s < 4; s++) mma16(tms, dqh + 2*s, dkl + 2*s, ID_128, 1);
#pragma unroll
                    for (int s = 0; s < 4; s++) mma16(tms, dql + 2*s, dkh + 2*s, ID_128, 1);
                    TC_COMMIT(sb + 8);
                }
                MBAR_WAIT(sb + 56, g & 1);             // P(g) stored
                MBAR_WAIT(sb + 40 + (g & 1) * 8, (g >> 1) & 1);   // V(g) resident
                FPROXY();
                {                                       // PV(g)
                    uint32_t vb0 = sb + A_V0 + (g & 1) * 32768;
                    uint64_t dvh = dk(vb0), dvl = dk(vb0 + 16384);
                    uint32_t dsto = tmo + (g >> 4) * 64;
                    int accbase = (g & 15) > 0;
#pragma unroll
                    for (int s = 0; s < 8; s++) {
                        uint64_t pa = (uint64_t)((s >> 2) * 1024 + (s & 3) * 2);
                        uint64_t vb = (uint64_t)((s >> 2) * 512  + (s & 3) * 2);
                        mma16(dsto, dph + pa, dvh + vb, ID_PV, accbase || (s > 0));
                    }
#pragma unroll
                    for (int s = 0; s < 8; s++) {
                        uint64_t pa = (uint64_t)((s >> 2) * 1024 + (s & 3) * 2);
                        uint64_t vb = (uint64_t)((s >> 2) * 512  + (s & 3) * 2);
                        mma16(dsto, dph + pa, dvl + vb, ID_PV, 1);
                    }
#pragma unroll
                    for (int s = 0; s < 8; s++) {
                        uint64_t pa = (uint64_t)((s >> 2) * 1024 + (s & 3) * 2);
                        uint64_t vb = (uint64_t)((s >> 2) * 512  + (s & 3) * 2);
                        mma16(dsto, dpl + pa, dvh + vb, ID_PV, 1);
                    }
                    TC_COMMIT(sb + 16);
                }
            }
        }
    } else {
        // ---------------- softmax / load warps ----------------
        const int r = (wid & 3) * 32 + lane;
        const int cb = (wid >> 2) * 32;
        for (int g = 0; g < NT; g++) {
            const int srcI = g >> 4;
            MBAR_WAIT(sb + 8, g & 1);                  // S(g) done
            TC_FA();
            if (g + 2 < NT) ldK(g + 2, g & 1);

            uint32_t u0[32];
            float ps = 0.0f;
            LDTM32(u0, tm + (g & 1) * 128 + cb);
            TC_WLD(); TC_FB();
#pragma unroll
            for (int j = 0; j < 16; j++) {
                float e0 = __expf(__uint_as_float(u0[2*j]));
                float e1 = __expf(__uint_as_float(u0[2*j + 1]));
                ps += e0 + e1;
                uint32_t hw = pack2(e0, e1);
                float h0 = __uint_as_float(hw << 16);
                float h1 = __uint_as_float(hw & 0xffff0000u);
                u0[2*j]     = hw;
                u0[2*j + 1] = pack2(e0 - h0, e1 - h1);
            }

            if (g >= 1) MBAR_WAIT(sb + 16, (g - 1) & 1);   // PV(g-1): P + V buf free
            if (g + 1 < NT) ldV(g + 1, (g + 1) & 1);

#pragma unroll
            for (int j4 = 0; j4 < 8; j4++) {
                int t = cb + j4 * 4;
                uint32_t off = (uint32_t)((t >> 6) * 16384) + SWZ(r * 128 + (t & 63) * 2);
                *(uint2*)(sm + A_PH + off) = make_uint2(u0[j4*4],     u0[j4*4 + 2]);
                *(uint2*)(sm + A_PL + off) = make_uint2(u0[j4*4 + 1], u0[j4*4 + 3]);
            }
            atomicAdd(&lsumf[srcI * 128 + r], ps);
            FPROXY();
            MBAR_ARRIVE(sb + 56);                      // P(g) ready
        }
    }

    __syncthreads();
    MBAR_WAIT(sb + 16, (NT - 1) & 1);   // PV(47) complete
    TC_FA();

    if (wid < 8) {
        const int r = (wid & 3) * 32 + lane;
        const int cb2 = (wid >> 2) * 32;
        float oacc[32];
#pragma unroll
        for (int j = 0; j < 32; j++) oacc[j] = 0.0f;
#pragma unroll
        for (int srcI = 0; srcI < 3; srcI++) {
            uint32_t uo[32];
            LDTM32(uo, tmo + srcI * 64 + cb2);
            TC_WLD();
            float inv = 1.0f / lsumf[srcI * 128 + r];
#pragma unroll
            for (int j = 0; j < 32; j++) oacc[j] += __uint_as_float(uo[j]) * inv;
        }
        TC_FB();

        uint32_t hw[16], lw[16];
#pragma unroll
        for (int j = 0; j < 16; j++) {
            __nv_bfloat16 h0 = __float2bfloat16_rn(oacc[2*j]), h1 = __float2bfloat16_rn(oacc[2*j+1]);
            hw[j] = packh(h0, h1);
            lw[j] = packh(__float2bfloat16_rn(oacc[2*j]   - __bfloat162float(h0)),
                          __float2bfloat16_rn(oacc[2*j+1] - __bfloat162float(h1)));
        }
        size_t o = (size_t)(b * 2048 + q0 + r) * 512 + h * 64 + cb2;
#pragma unroll
        for (int g2 = 0; g2 < 4; g2++) {
            *(uint4*)(oh + o + g2 * 8) = make_uint4(hw[g2*4], hw[g2*4+1], hw[g2*4+2], hw[g2*4+3]);
            *(uint4*)(ol + o + g2 * 8) = make_uint4(lw[g2*4], lw[g2*4+1], lw[g2*4+2], lw[g2*4+3]);
        }
    }
    __syncthreads();
    if (wid == 0) TC_DEALLOC(tm, 512);
}

// ---------------------------------------------------------------------------
extern "C" void kernel_launch(void* const* d_in, const int* in_sizes, int n_in,
                              void* d_out, int out_size)
{
    const float* x  = (const float*)d_in[0];
    const float* y  = (const float*)d_in[1];
    const float* Wq = (const float*)d_in[2];
    const float* bq = (const float*)d_in[3];
    const float* Wk = (const float*)d_in[4];
    const float* bk = (const float*)d_in[5];
    const float* Wv = (const float*)d_in[6];
    const float* bv = (const float*)d_in[7];
    const float* Wp = (const float*)d_in[8];
    const float* bp = (const float*)d_in[9];
    float* out = (float*)d_out;

    __nv_bfloat16 *xh, *xl, *yh, *yl, *wh, *wl, *Qh, *Ql, *Kh, *Kl, *Vth, *Vtl, *Oh, *Ol;
    cudaGetSymbolAddress((void**)&xh, g_xh);  cudaGetSymbolAddress((void**)&xl, g_xl);
    cudaGetSymbolAddress((void**)&yh, g_yh);  cudaGetSymbolAddress((void**)&yl, g_yl);
    cudaGetSymbolAddress((void**)&wh, g_wh);  cudaGetSymbolAddress((void**)&wl, g_wl);
    cudaGetSymbolAddress((void**)&Qh, g_qh);  cudaGetSymbolAddress((void**)&Ql, g_ql);
    cudaGetSymbolAddress((void**)&Kh, g_kh);  cudaGetSymbolAddress((void**)&Kl, g_kl);
    cudaGetSymbolAddress((void**)&Vth, g_vth); cudaGetSymbolAddress((void**)&Vtl, g_vtl);
    cudaGetSymbolAddress((void**)&Oh, g_oh);  cudaGetSymbolAddress((void**)&Ol, g_ol);

    cudaFuncSetAttribute(proj,   cudaFuncAttributeMaxDynamicSharedMemorySize, GSM);
    cudaFuncSetAttribute(tgemm0, cudaFuncAttributeMaxDynamicSharedMemorySize, GSM);
    cudaFuncSetAttribute(attn,   cudaFuncAttributeMaxDynamicSharedMemorySize, A_SMEM);

    splitk<<<512, 256>>>(x, xh, xl, ELEM_X / 4);
    splitk<<<1024, 256>>>(y, yh, yl, ELEM_Y / 4);
    wtsk<<<dim3(16, 16, 8), dim3(32, 32)>>>(Wq, Wk, Wv, Wp, wh, wl);

    proj<<<dim3(4, 32, 7), 256, GSM>>>(xh, xl, yh, yl, wh, wl, bq, bk, bv,
                                       Qh, Ql, Kh, Kl, Vth, Vtl);
    attn<<<dim3(16, 8, 2), 544, A_SMEM>>>(Qh, Ql, Kh, Kl, Vth, Vtl, Oh, Ol);
    tgemm0<<<dim3(4, 32), 256, GSM>>>(Oh, Ol, wh + 7 * WSTR, wl + 7 * WSTR, bp, out);
}

// round 17
// speedup vs baseline: 1.2542x; 1.2542x over previous
#include <cuda_runtime.h>
#include <cuda_bf16.h>
#include <cuda_fp16.h>
#include <stdint.h>

#define NSRC 3
#define ELEM_X (2*2048*512)
#define ELEM_Y (3*2*2048*512)
#define WSTR   (512*512)

__device__ __nv_bfloat16 g_xh[ELEM_X], g_xl[ELEM_X];
__device__ __nv_bfloat16 g_yh[ELEM_Y], g_yl[ELEM_Y];
__device__ __nv_bfloat16 g_wh[8*WSTR], g_wl[8*WSTR];
__device__ __half g_qf[ELEM_X];                      // fp16 Q
__device__ __half g_kf[ELEM_Y];                      // fp16 K
__device__ __half g_vf[ELEM_Y];                      // fp16 V^T: [src*512+n][4096]
__device__ __nv_bfloat16 g_oh[ELEM_X], g_ol[ELEM_X];

#define SWZ(o) ((uint32_t)(o) ^ ((((uint32_t)(o)) >> 3) & 0x70u))
#define ID_128  0x8200490u   /* kind::f16 f32acc bf16 M=128 N=128 */
#define IDF_128 0x8200010u   /* kind::f16 f32acc fp16 M=128 N=128 */
#define IDF_PV  0x8100010u   /* kind::f16 f32acc fp16 M=128 N=64  */

#if defined(__CUDA_ARCH_FEAT_SM103_ALL) || defined(__CUDA_ARCH_FEAT_SM100_ALL) || !defined(__CUDA_ARCH__)
#define HAS_TC5 1
#else
#define HAS_TC5 0
#endif

__device__ __forceinline__ uint32_t elect1() {
    uint32_t p;
    asm volatile("{\n\t.reg .pred p;\n\telect.sync _|p, 0xFFFFFFFF;\n\tselp.b32 %0,1,0,p;\n\t}" : "=r"(p));
    return p;
}
__device__ __forceinline__ uint32_t s2u(const void* p) {
    uint32_t a;
    asm("{ .reg .u64 t; cvta.to.shared.u64 t, %1; cvt.u32.u64 %0, t; }" : "=r"(a) : "l"(p));
    return a;
}
__device__ __forceinline__ uint64_t dk(uint32_t a) {
    return (2ull<<61)|(1ull<<46)|(64ull<<32)|(1ull<<16)|((uint64_t)(a>>4)&0x3FFFull);
}

#define MBAR_INIT(a,n) asm volatile("mbarrier.init.shared.b64 [%0], %1;" :: "r"(a), "r"(n) : "memory")
#define MBAR_WAIT(a,ph) asm volatile("{\n\t.reg .pred P1;\n\tLW%=:\n\t" \
    "mbarrier.try_wait.parity.acquire.cta.shared::cta.b64 P1, [%0], %1, 0x989680;\n\t" \
    "@P1 bra.uni LD%=;\n\tbra.uni LW%=;\n\tLD%=:\n\t}" :: "r"(a), "r"(ph) : "memory")
#define FPROXY()       asm volatile("fence.proxy.async.shared::cta;" ::: "memory")
#define CPA16(d,s)     asm volatile("cp.async.cg.shared.global [%0], [%1], 16;" :: "r"(d), "l"(s))
#define CPA_COMMIT()   asm volatile("cp.async.commit_group;" ::: "memory")
#define CPA_WAIT0()    asm volatile("cp.async.wait_group 0;" ::: "memory")
#define CPA_WAIT1()    asm volatile("cp.async.wait_group 1;" ::: "memory")
#define CPA_WAIT2()    asm volatile("cp.async.wait_group 2;" ::: "memory")
#define CPA_MBAR(a)    asm volatile("cp.async.mbarrier.arrive.noinc.shared::cta.b64 [%0];" :: "r"(a) : "memory")

#if HAS_TC5
__device__ __forceinline__ void mma16(uint32_t d, uint64_t a, uint64_t b, uint32_t id, uint32_t acc) {
    asm volatile("{\n\t.reg .pred p;\n\tsetp.ne.u32 p, %4, 0;\n\t"
        "tcgen05.mma.cta_group::1.kind::f16 [%0], %1, %2, %3, {%5,%5,%5,%5}, p;\n\t}"
        :: "r"(d), "l"(a), "l"(b), "r"(id), "r"(acc), "r"(0u) : "memory");
}
#define TC_ALLOC(a,n)  asm volatile("tcgen05.alloc.cta_group::1.sync.aligned.shared::cta.b32 [%0], %1;" :: "r"(a), "r"(n) : "memory")
#define TC_RELQ()      asm volatile("tcgen05.relinquish_alloc_permit.cta_group::1.sync.aligned;")
#define TC_DEALLOC(t,n) asm volatile("tcgen05.dealloc.cta_group::1.sync.aligned.b32 %0, %1;" :: "r"(t), "r"(n))
#define TC_COMMIT(a)   asm volatile("tcgen05.commit.cta_group::1.mbarrier::arrive::one.shared::cluster.b64 [%0];" :: "r"(a) : "memory")
#define TC_FA()        asm volatile("tcgen05.fence::after_thread_sync;" ::: "memory")
#define TC_FB()        asm volatile("tcgen05.fence::before_thread_sync;" ::: "memory")
#define TC_WLD()       asm volatile("tcgen05.wait::ld.sync.aligned;" ::: "memory")
#define LDTM32(r, a) asm volatile( \
    "tcgen05.ld.sync.aligned.32x32b.x32.b32 " \
    "{%0,%1,%2,%3,%4,%5,%6,%7,%8,%9,%10,%11,%12,%13,%14,%15," \
    "%16,%17,%18,%19,%20,%21,%22,%23,%24,%25,%26,%27,%28,%29,%30,%31}, [%32];" \
    : "=r"((r)[0]),"=r"((r)[1]),"=r"((r)[2]),"=r"((r)[3]),"=r"((r)[4]),"=r"((r)[5]),"=r"((r)[6]),"=r"((r)[7]), \
      "=r"((r)[8]),"=r"((r)[9]),"=r"((r)[10]),"=r"((r)[11]),"=r"((r)[12]),"=r"((r)[13]),"=r"((r)[14]),"=r"((r)[15]), \
      "=r"((r)[16]),"=r"((r)[17]),"=r"((r)[18]),"=r"((r)[19]),"=r"((r)[20]),"=r"((r)[21]),"=r"((r)[22]),"=r"((r)[23]), \
      "=r"((r)[24]),"=r"((r)[25]),"=r"((r)[26]),"=r"((r)[27]),"=r"((r)[28]),"=r"((r)[29]),"=r"((r)[30]),"=r"((r)[31]) \
    : "r"(a))
#else
__device__ __forceinline__ void mma16(uint32_t, uint64_t, uint64_t, uint32_t, uint32_t) { __trap(); }
#define TC_ALLOC(a,n)   __trap()
#define TC_RELQ()       __trap()
#define TC_DEALLOC(t,n) __trap()
#define TC_COMMIT(a)    __trap()
#define TC_FA()         ((void)0)
#define TC_FB()         ((void)0)
#define TC_WLD()        ((void)0)
#define LDTM32(r, a) do { _Pragma("unroll") for (int _i = 0; _i < 32; _i++) (r)[_i] = 0u; __trap(); } while (0)
#endif

__device__ __forceinline__ uint32_t packh(__nv_bfloat16 a, __nv_bfloat16 b) {
    __nv_bfloat162 v; v.x = a; v.y = b;
    return *reinterpret_cast<uint32_t*>(&v);
}
__device__ __forceinline__ uint32_t pack2h(float lo, float hi) {   // fp16x2
    __half2 v = __floats2half2_rn(lo, hi);
    return *reinterpret_cast<uint32_t*>(&v);
}

// ------------------------- prep kernels -----------------------------------
__global__ void splitk(const float* __restrict__ in, __nv_bfloat16* __restrict__ oh,
                       __nv_bfloat16* __restrict__ ol, int n4) {
    for (int i = blockIdx.x * blockDim.x + threadIdx.x; i < n4; i += gridDim.x * blockDim.x) {
        float4 v = ((const float4*)in)[i];
        __nv_bfloat16 h0 = __float2bfloat16_rn(v.x), h1 = __float2bfloat16_rn(v.y);
        __nv_bfloat16 h2 = __float2bfloat16_rn(v.z), h3 = __float2bfloat16_rn(v.w);
        __nv_bfloat16 l0 = __float2bfloat16_rn(v.x - __bfloat162float(h0));
        __nv_bfloat16 l1 = __float2bfloat16_rn(v.y - __bfloat162float(h1));
        __nv_bfloat16 l2 = __float2bfloat16_rn(v.z - __bfloat162float(h2));
        __nv_bfloat16 l3 = __float2bfloat16_rn(v.w - __bfloat162float(h3));
        *(uint2*)(oh + 4 * (size_t)i) = make_uint2(packh(h0, h1), packh(h2, h3));
        *(uint2*)(ol + 4 * (size_t)i) = make_uint2(packh(l0, l1), packh(l2, l3));
    }
}

__global__ void wtsk(const float* __restrict__ Wq, const float* __restrict__ Wk,
                     const float* __restrict__ Wv, const float* __restrict__ Wp,
                     __nv_bfloat16* __restrict__ th, __nv_bfloat16* __restrict__ tl) {
    __shared__ float t[32][33];
    int m = blockIdx.z;
    const float* Wm = (m == 0) ? Wq : (m <= 3) ? Wk + (size_t)(m - 1) * WSTR
                    : (m <= 6) ? Wv + (size_t)(m - 4) * WSTR : Wp;
    int k0 = blockIdx.x * 32, n0 = blockIdx.y * 32;
    t[threadIdx.y][threadIdx.x] = Wm[(size_t)(k0 + threadIdx.y) * 512 + n0 + threadIdx.x];
    __syncthreads();
    float v = t[threadIdx.x][threadIdx.y];
    size_t di = (size_t)m * WSTR + (size_t)(n0 + threadIdx.y) * 512 + k0 + threadIdx.x;
    __nv_bfloat16 h = __float2bfloat16_rn(v);
    th[di] = h;
    tl[di] = __float2bfloat16_rn(v - __bfloat162float(h));
}

// ------------------------- unified projection GEMM -------------------------
// z=0 Q (scale 1/8, fp16 out), z=1..3 K_i (fp16), z=4..6 V_i (fp16 transposed).
__global__ __launch_bounds__(256) void proj(
    const __nv_bfloat16* __restrict__ xh, const __nv_bfloat16* __restrict__ xl,
    const __nv_bfloat16* __restrict__ yh, const __nv_bfloat16* __restrict__ yl,
    const __nv_bfloat16* __restrict__ wh, const __nv_bfloat16* __restrict__ wl,
    const float* __restrict__ bq, const float* __restrict__ bk, const float* __restrict__ bv,
    __half* __restrict__ Qf, __half* __restrict__ Kf, __half* __restrict__ Vf)
{
    extern __shared__ char sm[];
    const uint32_t sb = s2u(sm);
    const int tid = threadIdx.x, wid = tid >> 5, lane = tid & 31;
    const int bm = blockIdx.y * 128, bn = blockIdx.x * 128;
    const int z = blockIdx.z;

    const __nv_bfloat16 *ah, *al, *bhp, *blp;
    const float* bias;
    __half* ohp;
    float scale;
    int mode;
    if (z == 0) {
        ah = xh; al = xl; bhp = wh; blp = wl; bias = bq;
        ohp = Qf; scale = 0.125f; mode = 1;
    } else if (z <= 3) {
        int s = z - 1; size_t off = (size_t)s * 2 * 2048 * 512;
        ah = yh + off; al = yl + off;
        bhp = wh + (size_t)(1 + s) * WSTR; blp = wl + (size_t)(1 + s) * WSTR;
        bias = bk + 512 * s; ohp = Kf + off; scale = 1.0f; mode = 1;
    } else {
        int s = z - 4; size_t off = (size_t)s * 2 * 2048 * 512;
        ah = yh + off; al = yl + off;
        bhp = wh + (size_t)(4 + s) * WSTR; blp = wl + (size_t)(4 + s) * WSTR;
        bias = bv + 512 * s; ohp = Vf + off; scale = 1.0f; mode = 2;
    }

    if (wid == 0) { TC_ALLOC(sb, 128); TC_RELQ(); }
    if (tid == 0) MBAR_INIT(sb + 8, 1);
    __syncthreads();
    uint32_t tm;
    asm volatile("ld.shared.b32 %0, [%1];" : "=r"(tm) : "r"(sb));

    auto stage = [&](int kc, int buf) {
#pragma unroll
        for (int i = 0; i < 16; i++) {
            int idx = tid + i * 256;
            int t = idx >> 10, r = (idx >> 3) & 127, u = idx & 7;
            const __nv_bfloat16* src = (t == 0) ? ah : (t == 1) ? al : (t == 2) ? bhp : blp;
            int grow = ((t < 2) ? bm : bn) + r;
            CPA16(sb + 1024 + buf * 65536 + t * 16384 + SWZ(r * 128 + u * 16),
                  src + (size_t)grow * 512 + kc * 64 + u * 8);
        }
        CPA_COMMIT();
    };

    stage(0, 0);
    stage(1, 1);
    for (int kc = 0; kc < 8; kc++) {
        int buf = kc % 3;
        if (kc >= 1) MBAR_WAIT(sb + 8, (kc - 1) & 1);
        if (kc + 2 < 8) stage(kc + 2, (kc + 2) % 3);
        if (kc < 6) CPA_WAIT2(); else if (kc == 6) CPA_WAIT1(); else CPA_WAIT0();
        FPROXY(); __syncthreads();
        if (wid == 0 && elect1()) {
            uint32_t ab = sb + 1024 + buf * 65536;
            uint64_t dah = dk(ab), dal = dk(ab + 16384);
            uint64_t dbh = dk(ab + 32768), dbl = dk(ab + 49152);
#pragma unroll
            for (int s = 0; s < 4; s++) mma16(tm, dah + 2*s, dbh + 2*s, ID_128, (kc > 0) || (s > 0));
#pragma unroll
            for (int s = 0; s < 4; s++) mma16(tm, dah + 2*s, dbl + 2*s, ID_128, 1);
#pragma unroll
            for (int s = 0; s < 4; s++) mma16(tm, dal + 2*s, dbh + 2*s, ID_128, 1);
            TC_COMMIT(sb + 8);
        }
    }
    MBAR_WAIT(sb + 8, 1);
    TC_FA();

    const int r = (wid & 3) * 32 + lane, cb = (wid >> 2) * 64;
    uint32_t u[64];
    LDTM32(u, tm + cb);
    LDTM32(u + 32, tm + cb + 32);
    TC_WLD(); TC_FB();
    float f[64];
#pragma unroll
    for (int j = 0; j < 64; j++)
        f[j] = scale * (__uint_as_float(u[j]) + bias[bn + cb + j]);
    if (mode == 1) {
        uint32_t hw[32];
#pragma unroll
        for (int j = 0; j < 32; j++) hw[j] = pack2h(f[2*j], f[2*j+1]);
        size_t o = (size_t)(bm + r) * 512 + bn + cb;
#pragma unroll
        for (int g = 0; g < 8; g++)
            *(uint4*)(ohp + o + g * 8) = make_uint4(hw[g*4], hw[g*4+1], hw[g*4+2], hw[g*4+3]);
    } else {
#pragma unroll
        for (int j = 0; j < 64; j++) {
            size_t o = (size_t)(bn + cb + j) * 4096 + bm + r;
            ohp[o] = __float2half_rn(f[j]);
        }
    }
    __syncthreads();
    if (wid == 0) TC_DEALLOC(tm, 128);
}

// ------------------------- out-projection GEMM (fp32 out) ------------------
__global__ __launch_bounds__(256) void tgemm0(
    const __nv_bfloat16* __restrict__ ah, const __nv_bfloat16* __restrict__ al,
    const __nv_bfloat16* __restrict__ bh, const __nv_bfloat16* __restrict__ bl,
    const float* __restrict__ bias, float* __restrict__ of)
{
    extern __shared__ char sm[];
    const uint32_t sb = s2u(sm);
    const int tid = threadIdx.x, wid = tid >> 5, lane = tid & 31;
    const int bm = blockIdx.y * 128, bn = blockIdx.x * 128;

    if (wid == 0) { TC_ALLOC(sb, 128); TC_RELQ(); }
    if (tid == 0) MBAR_INIT(sb + 8, 1);
    __syncthreads();
    uint32_t tm;
    asm volatile("ld.shared.b32 %0, [%1];" : "=r"(tm) : "r"(sb));

    auto stage = [&](int kc, int buf) {
#pragma unroll
        for (int i = 0; i < 16; i++) {
            int idx = tid + i * 256;
            int t = idx >> 10, r = (idx >> 3) & 127, u = idx & 7;
            const __nv_bfloat16* src = (t == 0) ? ah : (t == 1) ? al : (t == 2) ? bh : bl;
            int grow = ((t < 2) ? bm : bn) + r;
            CPA16(sb + 1024 + buf * 65536 + t * 16384 + SWZ(r * 128 + u * 16),
                  src + (size_t)grow * 512 + kc * 64 + u * 8);
        }
        CPA_COMMIT();
    };

    stage(0, 0);
    stage(1, 1);
    for (int kc = 0; kc < 8; kc++) {
        int buf = kc % 3;
        if (kc >= 1) MBAR_WAIT(sb + 8, (kc - 1) & 1);
        if (kc + 2 < 8) stage(kc + 2, (kc + 2) % 3);
        if (kc < 6) CPA_WAIT2(); else if (kc == 6) CPA_WAIT1(); else CPA_WAIT0();
        FPROXY(); __syncthreads();
        if (wid == 0 && elect1()) {
            uint32_t ab = sb + 1024 + buf * 65536;
            uint64_t dah = dk(ab), dal = dk(ab + 16384);
            uint64_t dbh = dk(ab + 32768), dbl = dk(ab + 49152);
#pragma unroll
            for (int s = 0; s < 4; s++) mma16(tm, dah + 2*s, dbh + 2*s, ID_128, (kc > 0) || (s > 0));
#pragma unroll
            for (int s = 0; s < 4; s++) mma16(tm, dah + 2*s, dbl + 2*s, ID_128, 1);
#pragma unroll
            for (int s = 0; s < 4; s++) mma16(tm, dal + 2*s, dbh + 2*s, ID_128, 1);
            TC_COMMIT(sb + 8);
        }
    }
    MBAR_WAIT(sb + 8, 1);
    TC_FA();

    const int r = (wid & 3) * 32 + lane, cb = (wid >> 2) * 64;
    uint32_t u[64];
    LDTM32(u, tm + cb);
    LDTM32(u + 32, tm + cb + 32);
    TC_WLD(); TC_FB();
    float* p = of + (size_t)(bm + r) * 512 + bn + cb;
#pragma unroll
    for (int g = 0; g < 16; g++) {
        float4 o4;
        o4.x = __uint_as_float(u[g*4+0]) + bias[bn + cb + g*4+0];
        o4.y = __uint_as_float(u[g*4+1]) + bias[bn + cb + g*4+1];
        o4.z = __uint_as_float(u[g*4+2]) + bias[bn + cb + g*4+2];
        o4.w = __uint_as_float(u[g*4+3]) + bias[bn + cb + g*4+3];
        *(float4*)(p + g * 4) = o4;
    }
    __syncthreads();
    if (wid == 0) TC_DEALLOC(tm, 128);
}
#define GSM (1024 + 3 * 65536)

// --------------- attention, all-fp16 inside (512 thr) ----------------------
// smem: hdr 2048, Q @2048 (16K), K @18432 (2x16K), V @51200 (2x16K), P @83968 (32K)
#define A_Q   2048
#define A_K0  18432
#define A_V0  51200
#define A_P   83968
#define A_SMEM 116736
#define NT 48

__global__ __launch_bounds__(512) void attn(
    const __half* __restrict__ qf,
    const __half* __restrict__ kf,
    const __half* __restrict__ vf,
    __nv_bfloat16* __restrict__ oh, __nv_bfloat16* __restrict__ ol)
{
    extern __shared__ char sm[];
    const uint32_t sb = s2u(sm);
    float* lsumf = (float*)(sm + 64);
    const int tid = threadIdx.x, wid = tid >> 5, lane = tid & 31;
    const int q0 = blockIdx.x * 128, h = blockIdx.y, b = blockIdx.z;

    if (wid == 0) { TC_ALLOC(sb, 512); TC_RELQ(); }
    if (tid == 0) {
        MBAR_INIT(sb + 8, 1);  MBAR_INIT(sb + 16, 1);
        MBAR_INIT(sb + 24, 512); MBAR_INIT(sb + 32, 512);
        MBAR_INIT(sb + 40, 512); MBAR_INIT(sb + 48, 512);
    }
    if (tid < 384) lsumf[tid] = 0.f;
    __syncthreads();
    uint32_t tm;
    asm volatile("ld.shared.b32 %0, [%1];" : "=r"(tm) : "r"(sb));
    const uint32_t tmo = tm + 256;   // 3 x 64 O cols

    auto ldK = [&](int g1, int buf) {
        int srcI = g1 >> 4, kt = g1 & 15;
        const size_t kvb = ((size_t)(srcI * 2 + b)) * 2048 * 512 + h * 64;
        uint32_t base = sb + A_K0 + buf * 16384;
#pragma unroll
        for (int i = 0; i < 2; i++) {
            int idx = tid + i * 512;
            int rr = idx >> 3, u = idx & 7;
            CPA16(base + SWZ(rr * 128 + u * 16),
                  kf + kvb + (size_t)(kt * 128 + rr) * 512 + u * 8);
        }
        CPA_MBAR(sb + 24 + buf * 8);
    };
    auto ldV = [&](int g1, int buf) {
        int srcI = g1 >> 4, kt = g1 & 15;
        const size_t vtb = ((size_t)(srcI * 512 + h * 64)) * 4096 + b * 2048;
        uint32_t base = sb + A_V0 + buf * 16384;
#pragma unroll
        for (int i = 0; i < 2; i++) {
            int idx = tid + i * 512;
            int d = idx >> 4, u = idx & 15;
            CPA16(base + (u >> 3) * 8192 + SWZ(d * 128 + (u & 7) * 16),
                  vf + vtb + (size_t)d * 4096 + kt * 128 + u * 8);
        }
        CPA_MBAR(sb + 40 + buf * 8);
    };

    // Q tile (fp16, once)
#pragma unroll
    for (int i = 0; i < 2; i++) {
        int idx = tid + i * 512;
        int r = idx >> 3, u = idx & 7;
        uint4 v = *(const uint4*)(qf + (size_t)(b * 2048 + q0 + r) * 512 + h * 64 + u * 8);
        *(uint4*)(sm + A_Q + SWZ(r * 128 + u * 16)) = v;
    }

    // prologue
    ldK(0, 0); ldV(0, 0); ldK(1, 1);
    FPROXY(); __syncthreads();
    if (wid == 0 && elect1()) {
        MBAR_WAIT(sb + 24, 0);
        FPROXY();
        uint64_t dq = dk(sb + A_Q), dkh0 = dk(sb + A_K0);
#pragma unroll
        for (int s = 0; s < 4; s++) mma16(tm, dq + 2*s, dkh0 + 2*s, IDF_128, s > 0);
        TC_COMMIT(sb + 8);
    }

    const int r = (wid & 3) * 32 + lane;
    const int cb = (wid >> 2) * 32;

    for (int g = 0; g < NT; g++) {
        const int srcI = g >> 4;
        MBAR_WAIT(sb + 8, g & 1);                     // S(g) done
        TC_FA();
        if (g + 2 < NT) ldK(g + 2, g & 1);

        if (g + 1 < NT && wid == 0 && elect1()) {     // S(g+1)
            MBAR_WAIT(sb + 24 + ((g + 1) & 1) * 8, ((g + 1) >> 1) & 1);
            FPROXY();
            uint64_t dq = dk(sb + A_Q), dkh1 = dk(sb + A_K0 + ((g + 1) & 1) * 16384);
            uint32_t tms = tm + ((g + 1) & 1) * 128;
#pragma unroll
            for (int s = 0; s < 4; s++) mma16(tms, dq + 2*s, dkh1 + 2*s, IDF_128, s > 0);
            TC_COMMIT(sb + 8);
        }

        uint32_t u0[32], hw[16];
        float ps = 0.0f;
        LDTM32(u0, tm + (g & 1) * 128 + cb);
        TC_WLD(); TC_FB();
#pragma unroll
        for (int j = 0; j < 16; j++) {
            float e0 = __expf(__uint_as_float(u0[2*j]));
            float e1 = __expf(__uint_as_float(u0[2*j + 1]));
            ps += e0 + e1;
            hw[j] = pack2h(e0, e1);
        }

        if (g >= 1) MBAR_WAIT(sb + 16, (g - 1) & 1);   // PV(g-1): P + V buf free
        if (g + 1 < NT) ldV(g + 1, (g + 1) & 1);

#pragma unroll
        for (int j4 = 0; j4 < 8; j4++) {
            int t = cb + j4 * 4;
            uint32_t off = (uint32_t)((t >> 6) * 16384) + SWZ(r * 128 + (t & 63) * 2);
            *(uint2*)(sm + A_P + off) = make_uint2(hw[2*j4], hw[2*j4 + 1]);
        }
        atomicAdd(&lsumf[srcI * 128 + r], ps);
        FPROXY(); __syncthreads();                     // P visible

        if (wid == 0 && elect1()) {                    // PV(g): 8 fp16 MMAs
            MBAR_WAIT(sb + 40 + (g & 1) * 8, (g >> 1) & 1);
            FPROXY();
            uint32_t vb0 = sb + A_V0 + (g & 1) * 16384;
            uint64_t dp = dk(sb + A_P), dv = dk(vb0);
            uint32_t dsto = tmo + srcI * 64;
            int accbase = (g & 15) > 0;
#pragma unroll
            for (int s = 0; s < 8; s++) {
                uint64_t pa = (uint64_t)((s >> 2) * 1024 + (s & 3) * 2);
                uint64_t vb = (uint64_t)((s >> 2) * 512  + (s & 3) * 2);
                mma16(dsto, dp + pa, dv + vb, IDF_PV, accbase || (s > 0));
            }
            TC_COMMIT(sb + 16);
        }
    }

    MBAR_WAIT(sb + 16, (NT - 1) & 1);
    TC_FA();
    __syncthreads();

    if (wid < 8) {
        const int cb2 = (wid >> 2) * 32;
        float oacc[32];
#pragma unroll
        for (int j = 0; j < 32; j++) oacc[j] = 0.0f;
#pragma unroll
        for (int srcI = 0; srcI < 3; srcI++) {
            uint32_t uo[32];
            LDTM32(uo, tmo + srcI * 64 + cb2);
            TC_WLD();
            float inv = 1.0f / lsumf[srcI * 128 + r];
#pragma unroll
            for (int j = 0; j < 32; j++) oacc[j] += __uint_as_float(uo[j]) * inv;
        }
        TC_FB();

        uint32_t hw2[16], lw2[16];
#pragma unroll
        for (int j = 0; j < 16; j++) {
            __nv_bfloat16 h0 = __float2bfloat16_rn(oacc[2*j]), h1 = __float2bfloat16_rn(oacc[2*j+1]);
            hw2[j] = packh(h0, h1);
            lw2[j] = packh(__float2bfloat16_rn(oacc[2*j]   - __bfloat162float(h0)),
                           __float2bfloat16_rn(oacc[2*j+1] - __bfloat162float(h1)));
        }
        size_t o = (size_t)(b * 2048 + q0 + r) * 512 + h * 64 + cb2;
#pragma unroll
        for (int g2 = 0; g2 < 4; g2++) {
            *(uint4*)(oh + o + g2 * 8) = make_uint4(hw2[g2*4], hw2[g2*4+1], hw2[g2*4+2], hw2[g2*4+3]);
            *(uint4*)(ol + o + g2 * 8) = make_uint4(lw2[g2*4], lw2[g2*4+1], lw2[g2*4+2], lw2[g2*4+3]);
        }
    }
    __syncthreads();
    if (wid == 0) TC_DEALLOC(tm, 512);
}

// ---------------------------------------------------------------------------
extern "C" void kernel_launch(void* const* d_in, const int* in_sizes, int n_in,
                              void* d_out, int out_size)
{
    const float* x  = (const float*)d_in[0];
    const float* y  = (const float*)d_in[1];
    const float* Wq = (const float*)d_in[2];
    const float* bq = (const float*)d_in[3];
    const float* Wk = (const float*)d_in[4];
    const float* bk = (const float*)d_in[5];
    const float* Wv = (const float*)d_in[6];
    const float* bv = (const float*)d_in[7];
    const float* Wp = (const float*)d_in[8];
    const float* bp = (const float*)d_in[9];
    float* out = (float*)d_out;

    __nv_bfloat16 *xh, *xl, *yh, *yl, *wh, *wl, *Oh, *Ol;
    __half *Qf, *Kf, *Vf;
    cudaGetSymbolAddress((void**)&xh, g_xh);  cudaGetSymbolAddress((void**)&xl, g_xl);
    cudaGetSymbolAddress((void**)&yh, g_yh);  cudaGetSymbolAddress((void**)&yl, g_yl);
    cudaGetSymbolAddress((void**)&wh, g_wh);  cudaGetSymbolAddress((void**)&wl, g_wl);
    cudaGetSymbolAddress((void**)&Qf, g_qf);  cudaGetSymbolAddress((void**)&Kf, g_kf);
    cudaGetSymbolAddress((void**)&Vf, g_vf);
    cudaGetSymbolAddress((void**)&Oh, g_oh);  cudaGetSymbolAddress((void**)&Ol, g_ol);

    cudaFuncSetAttribute(proj,   cudaFuncAttributeMaxDynamicSharedMemorySize, GSM);
    cudaFuncSetAttribute(tgemm0, cudaFuncAttributeMaxDynamicSharedMemorySize, GSM);
    cudaFuncSetAttribute(attn,   cudaFuncAttributeMaxDynamicSharedMemorySize, A_SMEM);

    splitk<<<512, 256>>>(x, xh, xl, ELEM_X / 4);
    splitk<<<1024, 256>>>(y, yh, yl, ELEM_Y / 4);
    wtsk<<<dim3(16, 16, 8), dim3(32, 32)>>>(Wq, Wk, Wv, Wp, wh, wl);

    proj<<<dim3(4, 32, 7), 256, GSM>>>(xh, xl, yh, yl, wh, wl, bq, bk, bv, Qf, Kf, Vf);
    attn<<<dim3(16, 8, 2), 512, A_SMEM>>>(Qf, Kf, Vf, Oh, Ol);
    tgemm0<<<dim3(4, 32), 256, GSM>>>(Oh, Ol, wh + 7 * WSTR, wl + 7 * WSTR, bp, out);
}